// round 5
// baseline (speedup 1.0000x reference)
#include <cuda_runtime.h>
#include <math_constants.h>

#define N_NODES 100000
#define N_EDGES 3200000
#define ED 128          // embed dim
#define NG 128          // num graphs
#define NC 10           // num classes
#define NB 129          // buckets = thresholds + 1
#define NHIST (NG * NB) // 16512
#define NSM 148         // persistent grid for edges2

typedef unsigned long long u64;

// Scratch (device globals — no allocations allowed)
__device__ float    g_s[N_NODES];            // s[n] = feat[n] + sum_in feat[src]
__device__ unsigned g_e[N_NODES];            // per node: enc24 (fixed-point s) <<8 | bucket
__device__ u64      g_hist0[NHIST];          // node self-terms, packed {sum<<24 | count}
__device__ u64      g_part[(size_t)NSM * NHIST]; // per-CTA partial hists (19.5 MB)
__device__ int      g_cnt[NG];               // nodes per graph
__device__ float    g_T[ED];                 // sorted thresholds
__device__ int      g_rank[ED];              // sorted position of threshold d
__device__ int      g_side[ED];              // 1: active = s > t (suffix); 0: prefix
__device__ int      g_bound[NG + 1];         // graph boundary table (gids sorted)

#define FP_SCALE 65536.0f
#define FP_BIAS  128.0f
#define FP_BIAS_FIX ((long long)(128 << 16))   // 2^23

// ---------------------------------------------------------------------------
// K0: fused setup: s=feat, zero hist0/cnt; block0: thresholds; block1: bounds
__global__ void k_setup(const float* __restrict__ feat,
                        const float* __restrict__ W1, const float* __restrict__ b1,
                        const int* __restrict__ gids) {
    int tid = threadIdx.x;
    int i = blockIdx.x * blockDim.x + tid;
    if (i < N_NODES) g_s[i] = feat[i];
    if (i < NHIST) g_hist0[i] = 0ull;
    if (i < NG) g_cnt[i] = 0;

    if (blockIdx.x == 0) {
        __shared__ float ts[ED];
        if (tid < ED) {
            float w = W1[tid], b = b1[tid];
            float t; int side;
            if (w > 0.f)      { t = -b / w; side = 1; }
            else if (w < 0.f) { t = -b / w; side = 0; }
            else              { side = 1; t = (b > 0.f) ? -CUDART_INF_F : CUDART_INF_F; }
            ts[tid] = t;
            g_side[tid] = side;
        }
        __syncthreads();
        if (tid < ED) {
            float t = ts[tid];
            int r = 0;
#pragma unroll 8
            for (int j = 0; j < ED; j++) {
                float tj = ts[j];
                r += (tj < t) || (tj == t && j < tid);
            }
            g_rank[tid] = r;
            g_T[r] = t;
        }
    } else if (blockIdx.x == 1) {
        if (tid <= NG) {
            int g = tid;
            int lo = 0, hi = N_NODES;
            while (lo < hi) {
                int mid = (lo + hi) >> 1;
                if (__ldg(&gids[mid]) < g) lo = mid + 1; else hi = mid;
            }
            g_bound[g] = lo;
        }
    }
}

// ---------------------------------------------------------------------------
// K1: edge pass 1 — s[dst] += feat[src].  8 edges/thread, gathers batched.
__global__ __launch_bounds__(256) void k_edges1(const int4* __restrict__ src4,
                                                const int4* __restrict__ dst4,
                                                const float* __restrict__ feat) {
    const int half = N_EDGES / 8;   // 400000 int4 groups per half
    int i = blockIdx.x * blockDim.x + threadIdx.x;
    if (i >= half) return;
    int4 sa = __ldg(&src4[i]);
    int4 ta = __ldg(&dst4[i]);
    int4 sb = __ldg(&src4[i + half]);
    int4 tb = __ldg(&dst4[i + half]);
    float f0 = __ldg(&feat[sa.x]);
    float f1 = __ldg(&feat[sa.y]);
    float f2 = __ldg(&feat[sa.z]);
    float f3 = __ldg(&feat[sa.w]);
    float f4 = __ldg(&feat[sb.x]);
    float f5 = __ldg(&feat[sb.y]);
    float f6 = __ldg(&feat[sb.z]);
    float f7 = __ldg(&feat[sb.w]);
    atomicAdd(&g_s[ta.x], f0);
    atomicAdd(&g_s[ta.y], f1);
    atomicAdd(&g_s[ta.z], f2);
    atomicAdd(&g_s[ta.w], f3);
    atomicAdd(&g_s[tb.x], f4);
    atomicAdd(&g_s[tb.y], f5);
    atomicAdd(&g_s[tb.z], f6);
    atomicAdd(&g_s[tb.w], f7);
}

// ---------------------------------------------------------------------------
// K2: per node — bucket search, encode (enc24<<8 | bucket), self term, counts
__global__ __launch_bounds__(256) void k_bucket(const int* __restrict__ gids) {
    __shared__ float T[ED];
    __shared__ int hcnt[NG];
    int tid = threadIdx.x;
    if (tid < ED) T[tid] = g_T[tid];
    if (tid < NG) hcnt[tid] = 0;
    __syncthreads();
    int n = blockIdx.x * 256 + tid;
    if (n < N_NODES) {
        float s = g_s[n];
        int b = 0;
#pragma unroll
        for (int st = 128; st > 0; st >>= 1) {
            int nb = b + st;
            if (nb <= ED && T[nb - 1] <= s) b = nb;
        }
        float sc = fminf(fmaxf(s, -FP_BIAS + 1.0f), FP_BIAS - 1.0f);
        unsigned enc = (unsigned)__float2int_rn((sc + FP_BIAS) * FP_SCALE);  // < 2^24
        g_e[n] = (enc << 8) | (unsigned)b;
        int g = gids[n];
        atomicAdd(&g_hist0[g * NB + b], ((u64)enc << 24) | 1ull);
        atomicAdd(&hcnt[g], 1);
    }
    __syncthreads();
    if (tid < NG && hcnt[tid]) atomicAdd(&g_cnt[tid], hcnt[tid]);
}

// ---------------------------------------------------------------------------
// K3: edge pass 2 — persistent CTAs, smem-private packed histogram.
__global__ __launch_bounds__(512) void k_edges2(const int4* __restrict__ src4,
                                                const int4* __restrict__ dst4) {
    extern __shared__ u64 sh[];
    u64* hist = sh;                       // NHIST u64 = 132096 B
    int* bnd = (int*)(sh + NHIST);        // NG+1 ints
    int tid = threadIdx.x;
    for (int i = tid; i < NHIST * 2; i += 512) ((unsigned*)hist)[i] = 0u;
    if (tid <= NG) bnd[tid] = g_bound[tid];
    __syncthreads();

    const int half = N_EDGES / 8;         // 400000
    const int stride = gridDim.x * 512;
#define WALK_AND_ADD(e, t) {                                                  \
        int tt = (t);                                                         \
        int g = (tt * NG) / N_NODES;                                          \
        while (bnd[g + 1] <= tt) g++;                                         \
        while (bnd[g] > tt) g--;                                              \
        atomicAdd(&hist[g * NB + (int)((e) & 0xFFu)],                         \
                  ((u64)((e) >> 8) << 24) | 1ull);                            \
    }
    for (int i = blockIdx.x * 512 + tid; i < half; i += stride) {
        int4 sa = __ldg(&src4[i]);
        int4 ta = __ldg(&dst4[i]);
        int4 sb = __ldg(&src4[i + half]);
        int4 tb = __ldg(&dst4[i + half]);
        unsigned e0 = __ldg(&g_e[sa.x]);
        unsigned e1 = __ldg(&g_e[sa.y]);
        unsigned e2 = __ldg(&g_e[sa.z]);
        unsigned e3 = __ldg(&g_e[sa.w]);
        unsigned e4 = __ldg(&g_e[sb.x]);
        unsigned e5 = __ldg(&g_e[sb.y]);
        unsigned e6 = __ldg(&g_e[sb.z]);
        unsigned e7 = __ldg(&g_e[sb.w]);
        WALK_AND_ADD(e0, ta.x);
        WALK_AND_ADD(e1, ta.y);
        WALK_AND_ADD(e2, ta.z);
        WALK_AND_ADD(e3, ta.w);
        WALK_AND_ADD(e4, tb.x);
        WALK_AND_ADD(e5, tb.y);
        WALK_AND_ADD(e6, tb.z);
        WALK_AND_ADD(e7, tb.w);
    }
#undef WALK_AND_ADD
    __syncthreads();
    // flush private hist (non-atomic, coalesced) to this CTA's partial slice
    u64* mypart = g_part + (size_t)blockIdx.x * NHIST;
#pragma unroll 4
    for (int i = tid; i < NHIST; i += 512) mypart[i] = hist[i];
}

// ---------------------------------------------------------------------------
// K4: per graph — reduce partials + hist0, decode, suffix sums, head MLPs
__global__ __launch_bounds__(128) void k_final(const float* __restrict__ W1,
                                               const float* __restrict__ b1,
                                               const float* __restrict__ W2,
                                               const float* __restrict__ b2,
                                               const float* __restrict__ Wf1,
                                               const float* __restrict__ bf1,
                                               const float* __restrict__ Wf2,
                                               const float* __restrict__ bf2,
                                               float* __restrict__ out) {
    __shared__ float bs[NB], bc[NB];
    __shared__ float suffS[NB + 1], suffC[NB + 1];
    __shared__ float a_sh[ED], h_sh[ED];
    int g = blockIdx.x;
    int d = threadIdx.x;

    for (int idx = d; idx < NB; idx += ED) {
        int off = g * NB + idx;
        long long accS = 0;
        long long accC = 0;
        {
            u64 h = g_hist0[off];
            accC += (long long)(h & 0xFFFFFFull);
            accS += (long long)(h >> 24);
        }
#pragma unroll 4
        for (int r = 0; r < NSM; r++) {
            u64 h = g_part[(size_t)r * NHIST + off];
            accC += (long long)(h & 0xFFFFFFull);
            accS += (long long)(h >> 24);
        }
        long long sfix = accS - accC * FP_BIAS_FIX;
        bs[idx] = (float)sfix * (1.0f / FP_SCALE);
        bc[idx] = (float)accC;
    }
    __syncthreads();
    if (d == 0) {
        double as = 0.0, ac = 0.0;
        suffS[NB] = 0.f; suffC[NB] = 0.f;
        for (int k = NB - 1; k >= 0; k--) {
            as += (double)bs[k]; ac += (double)bc[k];
            suffS[k] = (float)as; suffC[k] = (float)ac;
        }
    }
    __syncthreads();

    // hg[g,d] = (W1[d]*S_active + b1[d]*C_active) / count[g]
    {
        float w = W1[d], b = b1[d];
        int r = g_rank[d];
        float S = suffS[r + 1], C = suffC[r + 1];
        if (!g_side[d]) { S = suffS[0] - S; C = suffC[0] - C; }
        float invc = 1.0f / fmaxf((float)g_cnt[g], 1.0f);
        a_sh[d] = (w * S + b * C) * invc;
    }
    __syncthreads();

    float acc = b2[d];
#pragma unroll 8
    for (int k = 0; k < ED; k++) acc = fmaf(a_sh[k], W2[k * ED + d], acc);
    h_sh[d] = acc;
    __syncthreads();

    acc = bf1[d];
#pragma unroll 8
    for (int k = 0; k < ED; k++) acc = fmaf(h_sh[k], Wf1[k * ED + d], acc);
    acc = fmaxf(acc, 0.0f);
    __syncthreads();
    a_sh[d] = acc;
    __syncthreads();

    if (d < NC) {
        float o = bf2[d];
#pragma unroll 8
        for (int k = 0; k < ED; k++) o = fmaf(a_sh[k], Wf2[k * NC + d], o);
        out[g * NC + d] = o;
    }
}

// ---------------------------------------------------------------------------
extern "C" void kernel_launch(void* const* d_in, const int* in_sizes, int n_in,
                              void* d_out, int out_size) {
    const float* feat = (const float*)d_in[0];
    const int*   src  = (const int*)d_in[1];
    const int*   dst  = (const int*)d_in[2];
    const int*   gids = (const int*)d_in[3];
    const float* W1   = (const float*)d_in[4];
    const float* b1   = (const float*)d_in[5];
    const float* W2   = (const float*)d_in[6];
    const float* b2   = (const float*)d_in[7];
    const float* Wf1  = (const float*)d_in[8];
    const float* bf1  = (const float*)d_in[9];
    const float* Wf2  = (const float*)d_in[10];
    const float* bf2  = (const float*)d_in[11];
    float* out = (float*)d_out;

    const int smem_e2 = NHIST * sizeof(u64) + (NG + 2) * sizeof(int);
    static bool attr_done = false;
    if (!attr_done) {
        cudaFuncSetAttribute(k_edges2, cudaFuncAttributeMaxDynamicSharedMemorySize, smem_e2);
        attr_done = true;
    }

    k_setup<<<(N_NODES + 255) / 256, 256>>>(feat, W1, b1, gids);
    k_edges1<<<(N_EDGES / 8 + 255) / 256, 256>>>((const int4*)src, (const int4*)dst, feat);
    k_bucket<<<(N_NODES + 255) / 256, 256>>>(gids);
    k_edges2<<<NSM, 512, smem_e2>>>((const int4*)src, (const int4*)dst);
    k_final<<<NG, ED>>>(W1, b1, W2, b2, Wf1, bf1, Wf2, bf2, out);
}